// round 9
// baseline (speedup 1.0000x reference)
#include <cuda_runtime.h>
#include <cuda_fp16.h>
#include <cstdint>

#define B_BATCH 64
#define C_CH    862
#define S_LEN   720
#define P_OUT   336
#define G_CL    8
#define KC      32
#define NCHK    23          // ceil(720/32); chunk 22 is half zero-padded
#define K_PAD   736
#define MAX_TASKS 435
#define THREADS 256
#define N_HALF  168

// ---------------- device scratch ----------------
__device__ int g_task_c0[MAX_TASKS];
__device__ int g_task_c1[MAX_TASKS];
__device__ int g_task_g[MAX_TASKS];
__device__ int g_cl[C_CH];
__device__ int g_order[C_CH];
__device__ int g_cnt[G_CL];
__device__ int g_off[G_CL];
__device__ int g_pairoff[G_CL + 1];
__device__ int g_cursor[G_CL];

// Pre-converted W (fp16), K padded to 736 with zeros. ~4 MB static.
__device__ __half g_Wh[G_CL * P_OUT * K_PAD];

// ---------------- helpers ----------------
__device__ __forceinline__ uint32_t smem_u32(const void* p) {
    uint32_t a;
    asm("{ .reg .u64 t; cvta.to.shared.u64 t, %1; cvt.u32.u64 %0, t; }" : "=r"(a) : "l"(p));
    return a;
}
__device__ __forceinline__ uint32_t swz64(uint32_t o) { return o ^ ((o >> 3) & 0x30); }

__device__ __forceinline__ void ldsm4(uint32_t* r, uint32_t addr) {
    asm volatile("ldmatrix.sync.aligned.m8n8.x4.shared.b16 {%0,%1,%2,%3}, [%4];"
                 : "=r"(r[0]), "=r"(r[1]), "=r"(r[2]), "=r"(r[3]) : "r"(addr));
}
__device__ __forceinline__ void ldsm2(uint32_t* r, uint32_t addr) {
    asm volatile("ldmatrix.sync.aligned.m8n8.x2.shared.b16 {%0,%1}, [%2];"
                 : "=r"(r[0]), "=r"(r[1]) : "r"(addr));
}
__device__ __forceinline__ void mma16816(float* c, const uint32_t* a, uint32_t b0, uint32_t b1) {
    asm volatile(
        "mma.sync.aligned.m16n8k16.row.col.f32.f16.f16.f32 "
        "{%0,%1,%2,%3}, {%4,%5,%6,%7}, {%8,%9}, {%0,%1,%2,%3};"
        : "+f"(c[0]), "+f"(c[1]), "+f"(c[2]), "+f"(c[3])
        : "r"(a[0]), "r"(a[1]), "r"(a[2]), "r"(a[3]), "r"(b0), "r"(b1));
}
__device__ __forceinline__ void cpasync16(uint32_t dst, const void* src) {
    asm volatile("cp.async.cg.shared.global [%0], [%1], 16;" :: "r"(dst), "l"(src) : "memory");
}
__device__ __forceinline__ void cp_commit() { asm volatile("cp.async.commit_group;" ::: "memory"); }
__device__ __forceinline__ void cp_wait0()  { asm volatile("cp.async.wait_group 0;" ::: "memory"); }

__device__ __forceinline__ uint32_t pack2h(__half a, __half b) {
    uint16_t ua = *reinterpret_cast<uint16_t*>(&a);
    uint16_t ub = *reinterpret_cast<uint16_t*>(&b);
    return (uint32_t)ua | ((uint32_t)ub << 16);
}

// ---------------- SMEM layout (per 256-thr CTA) ----------------
#define SM_BIAS   0          // 168 * 4 = 672
#define SM_BUF0   1024
#define OFF_A     0          // 128 rows * 64B = 8192
#define OFF_B     8192       // 168 rows * 64B = 10752
#define BUF_BYTES 18944
#define SMEM_TOTAL (SM_BUF0 + 2 * BUF_BYTES)  // 38912

// ---------------- fused: W fp32 -> fp16 (blocks 0..N-2) + prep (last block) ----------------
#define CONV_TOTAL (G_CL * P_OUT * K_PAD)
#define CONV_BLOCKS ((CONV_TOTAL + 255) / 256)

__global__ void prep_conv_kernel(const float* __restrict__ W, const int* __restrict__ cl) {
    if (blockIdx.x < CONV_BLOCKS) {
        int idx = blockIdx.x * 256 + threadIdx.x;
        if (idx < CONV_TOTAL) {
            int k = idx % K_PAD;
            int row = idx / K_PAD;
            float v = (k < S_LEN) ? W[(size_t)row * S_LEN + k] : 0.0f;
            g_Wh[idx] = __float2half(v);
        }
        return;
    }
    // ---- prep block ----
    __shared__ int is64_s;
    const int tid = threadIdx.x;
    if (tid == 0) {
        int odd_zero = 1;
        #pragma unroll
        for (int i = 1; i < 32; i += 2) odd_zero &= (cl[i] == 0);
        is64_s = odd_zero;
    }
    if (tid < G_CL) { g_cnt[tid] = 0; g_cursor[tid] = 0; }
    __syncthreads();
    const int is64 = is64_s;
    for (int c = tid; c < C_CH; c += blockDim.x) {
        int g = is64 ? cl[2 * c] : cl[c];
        g_cl[c] = g;
        atomicAdd(&g_cnt[g], 1);
    }
    __syncthreads();
    if (tid == 0) {
        int o = 0, po = 0;
        for (int g = 0; g < G_CL; g++) {
            g_off[g] = o; g_pairoff[g] = po;
            o += g_cnt[g]; po += (g_cnt[g] + 1) >> 1;
        }
        g_pairoff[G_CL] = po;
    }
    __syncthreads();
    for (int c = tid; c < C_CH; c += blockDim.x) {
        int g = g_cl[c];
        int pos = g_off[g] + atomicAdd(&g_cursor[g], 1);
        g_order[pos] = c;
    }
    __syncthreads();
    const int total = g_pairoff[G_CL];
    for (int t = tid; t < MAX_TASKS; t += blockDim.x) {
        int c0 = -1, c1 = -1, gg = 0;
        if (t < total) {
            int g = 0;
            while (t >= g_pairoff[g + 1]) g++;
            int p = t - g_pairoff[g];
            c0 = g_order[g_off[g] + 2 * p];
            c1 = (2 * p + 1 < g_cnt[g]) ? g_order[g_off[g] + 2 * p + 1] : -1;
            gg = g;
        }
        g_task_c0[t] = c0; g_task_c1[t] = c1; g_task_g[t] = gg;
    }
}

// ---------------- main GEMM kernel (fp16 mma, 2 CTAs/SM) ----------------
__global__ __launch_bounds__(THREADS, 2)
void mm_kernel(const float* __restrict__ x,
               const float* __restrict__ bias,
               float* __restrict__ out) {
    const int task = blockIdx.x;
    const int c0 = g_task_c0[task];
    if (c0 < 0) return;
    const int c1 = g_task_c1[task];
    const int g  = g_task_g[task];
    const int p0 = blockIdx.y * N_HALF;

    extern __shared__ char smem[];
    const uint32_t sbase = smem_u32(smem);
    const int tid  = threadIdx.x;
    const int lane = tid & 31;
    const int wid  = tid >> 5;       // warp_m: 8 m-slices of 16 rows

    for (int j = tid; j < N_HALF; j += THREADS)
        *reinterpret_cast<float*>(smem + SM_BIAS + 4 * j) = bias[g * P_OUT + p0 + j];

    // Per-lane swizzled base offsets (chunk-invariant).
    const uint32_t a_swz  = swz64((uint32_t)((wid * 16 + (lane & 15)) * 64 + ((lane >> 4) & 1) * 16));
    const uint32_t b_swz  = swz64((uint32_t)((((lane >> 4) & 1) * 8 + (lane & 7)) * 64 + ((lane >> 3) & 1) * 16));
    const uint32_t b2_swz = swz64((uint32_t)((lane & 7) * 64 + ((lane >> 3) & 1) * 16));

    const __half* wh = g_Wh + ((size_t)g * P_OUT + p0) * K_PAD;

    float acc[21][4];
    #pragma unroll
    for (int i = 0; i < 21; i++)
        #pragma unroll
        for (int j = 0; j < 4; j++) acc[i][j] = 0.0f;

    // A load geometry: 256 threads, 4 units each: row = unit*32 + (tid>>3), col4 = (tid&7)*4.
    const int a_row = tid >> 3;          // 0..31
    const int a_col4 = (tid & 7) << 2;

    auto loadA = [&](int chunk, int buf) {
        char* bptr = smem + SM_BUF0 + buf * BUF_BYTES + OFF_A;
        const int k0 = chunk * KC;
        const bool kok = (k0 + a_col4 + 3) < S_LEN;
        #pragma unroll
        for (int it = 0; it < 4; it++) {
            const int row = it * 32 + a_row;           // 0..127
            const int ch = (row < 64) ? c0 : c1;
            float4 v = make_float4(0.f, 0.f, 0.f, 0.f);
            if (kok && ch >= 0)
                v = *reinterpret_cast<const float4*>(
                        x + ((size_t)(row & 63) * C_CH + ch) * S_LEN + k0 + a_col4);
            uint2 hp;
            hp.x = pack2h(__float2half(v.x), __float2half(v.y));
            hp.y = pack2h(__float2half(v.z), __float2half(v.w));
            *reinterpret_cast<uint2*>(bptr + swz64((uint32_t)(row * 64 + a_col4 * 2))) = hp;
        }
    };
    auto issueB = [&](int chunk, int buf) {
        const uint32_t bufb = sbase + SM_BUF0 + buf * BUF_BYTES + OFF_B;
        const int k0 = chunk * KC;
        #pragma unroll
        for (int it = 0; it < 3; it++) {
            int e = tid + it * THREADS;          // 0..671
            if (e < N_HALF * 4) {
                int row = e >> 2;
                int unit = e & 3;
                uint32_t dst = bufb + swz64((uint32_t)(row * 64 + unit * 16));
                cpasync16(dst, wh + (size_t)row * K_PAD + k0 + unit * 8);
            }
        }
        cp_commit();
    };

    // ---- pipeline prologue ----
    loadA(0, 0);
    issueB(0, 0);

    for (int i = 0; i < NCHK; i++) {
        const int buf = i & 1;
        const bool more = (i + 1 < NCHK);
        cp_wait0();                            // B(i) landed
        __syncthreads();                       // all warps past chunk i-1; buf^1 free
        if (more) { loadA(i + 1, buf ^ 1); issueB(i + 1, buf ^ 1); }

        const uint32_t bufb = sbase + SM_BUF0 + buf * BUF_BYTES;
        #pragma unroll
        for (int k16 = 0; k16 < 2; k16++) {
            const uint32_t ko = (uint32_t)(k16 << 5);
            uint32_t ah[4];
            ldsm4(ah, bufb + OFF_A + (a_swz ^ ko));
            const uint32_t bb = bufb + OFF_B;
            #pragma unroll
            for (int p = 0; p < 10; p += 2) {
                uint32_t bh0[4], bh1[4];
                ldsm4(bh0, bb + p * 1024 + (b_swz ^ ko));
                ldsm4(bh1, bb + (p + 1) * 1024 + (b_swz ^ ko));
                mma16816(acc[2 * p],     ah, bh0[0], bh0[1]);
                mma16816(acc[2 * p + 1], ah, bh0[2], bh0[3]);
                mma16816(acc[2 * p + 2], ah, bh1[0], bh1[1]);
                mma16816(acc[2 * p + 3], ah, bh1[2], bh1[3]);
            }
            uint32_t bh2[2];
            ldsm2(bh2, bb + 10240 + (b2_swz ^ ko));
            mma16816(acc[20], ah, bh2[0], bh2[1]);
        }
    }

    // ---- epilogue ----
    const int chan = (wid < 4) ? c0 : c1;
    if (chan < 0) return;
    const int r0 = wid * 16 + (lane >> 2);           // 0..127
    const int ncol = p0 + (lane & 3) * 2;
    float* o0 = out + ((size_t)(r0 & 63) * C_CH + chan) * P_OUT + ncol;
    float* o1 = out + ((size_t)((r0 + 8) & 63) * C_CH + chan) * P_OUT + ncol;
    const char* bsm = smem + SM_BIAS + 4 * (lane & 3) * 2;
    #pragma unroll
    for (int nf = 0; nf < 21; nf++) {
        float2 bv = *reinterpret_cast<const float2*>(bsm + nf * 32);
        float2 v0 = make_float2(acc[nf][0] + bv.x, acc[nf][1] + bv.y);
        float2 v1 = make_float2(acc[nf][2] + bv.x, acc[nf][3] + bv.y);
        *reinterpret_cast<float2*>(o0 + nf * 8) = v0;
        *reinterpret_cast<float2*>(o1 + nf * 8) = v1;
    }
}

extern "C" void kernel_launch(void* const* d_in, const int* in_sizes, int n_in,
                              void* d_out, int out_size) {
    const float* x        = (const float*)d_in[0];
    const int*   clusters = (const int*)d_in[1];   // int32 or int64; decoded on device
    const float* W        = (const float*)d_in[2];
    const float* bias     = (const float*)d_in[3];
    float*       out      = (float*)d_out;

    cudaFuncSetAttribute(mm_kernel, cudaFuncAttributeMaxDynamicSharedMemorySize, SMEM_TOTAL);

    prep_conv_kernel<<<CONV_BLOCKS + 1, 256>>>(W, clusters);
    dim3 grid(MAX_TASKS, 2);   // (task, N-half)
    mm_kernel<<<grid, THREADS, SMEM_TOTAL>>>(x, bias, out);
}

// round 10
// speedup vs baseline: 1.7390x; 1.7390x over previous
#include <cuda_runtime.h>
#include <cuda_fp16.h>
#include <cstdint>

#define B_BATCH 64
#define C_CH    862
#define S_LEN   720
#define P_OUT   336
#define G_CL    8
#define KC      32
#define NCHK    23          // ceil(720/32); chunk 22 is half zero-padded
#define K_PAD   736
#define MAX_TASKS 435
#define THREADS 256
#define N_HALF  168

// ---------------- device scratch ----------------
__device__ int g_task_c0[MAX_TASKS];
__device__ int g_task_c1[MAX_TASKS];
__device__ int g_task_g[MAX_TASKS];
__device__ int g_cl[C_CH];
__device__ int g_order[C_CH];
__device__ int g_cnt[G_CL];
__device__ int g_off[G_CL];
__device__ int g_pairoff[G_CL + 1];
__device__ int g_cursor[G_CL];

// Pre-converted W (fp16), K padded to 736 with zeros. ~4 MB static.
__device__ __half g_Wh[G_CL * P_OUT * K_PAD];

// ---------------- helpers ----------------
__device__ __forceinline__ uint32_t smem_u32(const void* p) {
    uint32_t a;
    asm("{ .reg .u64 t; cvta.to.shared.u64 t, %1; cvt.u32.u64 %0, t; }" : "=r"(a) : "l"(p));
    return a;
}
__device__ __forceinline__ uint32_t swz64(uint32_t o) { return o ^ ((o >> 3) & 0x30); }

__device__ __forceinline__ void ldsm4(uint32_t* r, uint32_t addr) {
    asm volatile("ldmatrix.sync.aligned.m8n8.x4.shared.b16 {%0,%1,%2,%3}, [%4];"
                 : "=r"(r[0]), "=r"(r[1]), "=r"(r[2]), "=r"(r[3]) : "r"(addr));
}
__device__ __forceinline__ void ldsm2(uint32_t* r, uint32_t addr) {
    asm volatile("ldmatrix.sync.aligned.m8n8.x2.shared.b16 {%0,%1}, [%2];"
                 : "=r"(r[0]), "=r"(r[1]) : "r"(addr));
}
__device__ __forceinline__ void mma16816(float* c, const uint32_t* a, uint32_t b0, uint32_t b1) {
    asm volatile(
        "mma.sync.aligned.m16n8k16.row.col.f32.f16.f16.f32 "
        "{%0,%1,%2,%3}, {%4,%5,%6,%7}, {%8,%9}, {%0,%1,%2,%3};"
        : "+f"(c[0]), "+f"(c[1]), "+f"(c[2]), "+f"(c[3])
        : "r"(a[0]), "r"(a[1]), "r"(a[2]), "r"(a[3]), "r"(b0), "r"(b1));
}
__device__ __forceinline__ void cpasync16(uint32_t dst, const void* src) {
    asm volatile("cp.async.cg.shared.global [%0], [%1], 16;" :: "r"(dst), "l"(src) : "memory");
}
__device__ __forceinline__ void cp_commit() { asm volatile("cp.async.commit_group;" ::: "memory"); }
__device__ __forceinline__ void cp_wait0()  { asm volatile("cp.async.wait_group 0;" ::: "memory"); }

__device__ __forceinline__ uint32_t pack2h(__half a, __half b) {
    uint16_t ua = *reinterpret_cast<uint16_t*>(&a);
    uint16_t ub = *reinterpret_cast<uint16_t*>(&b);
    return (uint32_t)ua | ((uint32_t)ub << 16);
}

// ---------------- SMEM layout (per 256-thr CTA) ----------------
#define SM_BIAS   0          // 168 * 4 = 672
#define SM_BUF0   1024
#define OFF_A     0          // 128 rows * 64B = 8192
#define OFF_B     8192       // 168 rows * 64B = 10752
#define BUF_BYTES 18944
#define SMEM_TOTAL (SM_BUF0 + 2 * BUF_BYTES)  // 38912

// ---------------- fused: W fp32 -> fp16 (blocks 0..N-2) + prep (last block) ----------------
#define CONV_TOTAL (G_CL * P_OUT * K_PAD)
#define CONV_BLOCKS ((CONV_TOTAL + 255) / 256)

__global__ void prep_conv_kernel(const float* __restrict__ W, const int* __restrict__ cl) {
    if (blockIdx.x < CONV_BLOCKS) {
        int idx = blockIdx.x * 256 + threadIdx.x;
        if (idx < CONV_TOTAL) {
            int k = idx % K_PAD;
            int row = idx / K_PAD;
            float v = (k < S_LEN) ? W[(size_t)row * S_LEN + k] : 0.0f;
            g_Wh[idx] = __float2half(v);
        }
        return;
    }
    // ---- prep block ----
    __shared__ int is64_s;
    const int tid = threadIdx.x;
    if (tid == 0) {
        int odd_zero = 1;
        #pragma unroll
        for (int i = 1; i < 32; i += 2) odd_zero &= (cl[i] == 0);
        is64_s = odd_zero;
    }
    if (tid < G_CL) { g_cnt[tid] = 0; g_cursor[tid] = 0; }
    __syncthreads();
    const int is64 = is64_s;
    for (int c = tid; c < C_CH; c += blockDim.x) {
        int g = is64 ? cl[2 * c] : cl[c];
        g_cl[c] = g;
        atomicAdd(&g_cnt[g], 1);
    }
    __syncthreads();
    if (tid == 0) {
        int o = 0, po = 0;
        for (int g = 0; g < G_CL; g++) {
            g_off[g] = o; g_pairoff[g] = po;
            o += g_cnt[g]; po += (g_cnt[g] + 1) >> 1;
        }
        g_pairoff[G_CL] = po;
    }
    __syncthreads();
    for (int c = tid; c < C_CH; c += blockDim.x) {
        int g = g_cl[c];
        int pos = g_off[g] + atomicAdd(&g_cursor[g], 1);
        g_order[pos] = c;
    }
    __syncthreads();
    const int total = g_pairoff[G_CL];
    for (int t = tid; t < MAX_TASKS; t += blockDim.x) {
        int c0 = -1, c1 = -1, gg = 0;
        if (t < total) {
            int g = 0;
            while (t >= g_pairoff[g + 1]) g++;
            int p = t - g_pairoff[g];
            c0 = g_order[g_off[g] + 2 * p];
            c1 = (2 * p + 1 < g_cnt[g]) ? g_order[g_off[g] + 2 * p + 1] : -1;
            gg = g;
        }
        g_task_c0[t] = c0; g_task_c1[t] = c1; g_task_g[t] = gg;
    }
}

// ---------------- main GEMM kernel (fp16 mma, 2 CTAs/SM, LDG-hiding pipeline) ----------------
__global__ __launch_bounds__(THREADS, 2)
void mm_kernel(const float* __restrict__ x,
               const float* __restrict__ bias,
               float* __restrict__ out) {
    const int task = blockIdx.x;
    const int c0 = g_task_c0[task];
    if (c0 < 0) return;
    const int c1 = g_task_c1[task];
    const int g  = g_task_g[task];
    const int p0 = blockIdx.y * N_HALF;

    extern __shared__ char smem[];
    const uint32_t sbase = smem_u32(smem);
    const int tid  = threadIdx.x;
    const int lane = tid & 31;
    const int wid  = tid >> 5;       // warp_m: 8 m-slices of 16 rows

    for (int j = tid; j < N_HALF; j += THREADS)
        *reinterpret_cast<float*>(smem + SM_BIAS + 4 * j) = bias[g * P_OUT + p0 + j];

    // Per-lane swizzled base offsets (chunk-invariant).
    const uint32_t a_swz  = swz64((uint32_t)((wid * 16 + (lane & 15)) * 64 + ((lane >> 4) & 1) * 16));
    const uint32_t b_swz  = swz64((uint32_t)((((lane >> 4) & 1) * 8 + (lane & 7)) * 64 + ((lane >> 3) & 1) * 16));
    const uint32_t b2_swz = swz64((uint32_t)((lane & 7) * 64 + ((lane >> 3) & 1) * 16));

    const __half* wh = g_Wh + ((size_t)g * P_OUT + p0) * K_PAD;

    float acc[21][4];
    #pragma unroll
    for (int i = 0; i < 21; i++)
        #pragma unroll
        for (int j = 0; j < 4; j++) acc[i][j] = 0.0f;

    // A load geometry: 256 threads, 4 units each: row = unit*32 + (tid>>3), col4 = (tid&7)*4.
    const int a_row = tid >> 3;          // 0..31
    const int a_col4 = (tid & 7) << 2;
    float4 aregs[4];                     // in-flight A values (LDG under MMAs)

    auto ldgA = [&](int chunk) {
        const int k0 = chunk * KC;
        const bool kok = (k0 + a_col4 + 3) < S_LEN;
        #pragma unroll
        for (int it = 0; it < 4; it++) {
            const int row = it * 32 + a_row;           // 0..127
            const int ch = (row < 64) ? c0 : c1;
            aregs[it] = make_float4(0.f, 0.f, 0.f, 0.f);
            if (kok && ch >= 0)
                aregs[it] = *reinterpret_cast<const float4*>(
                        x + ((size_t)(row & 63) * C_CH + ch) * S_LEN + k0 + a_col4);
        }
    };
    auto stA = [&](int buf) {
        char* bptr = smem + SM_BUF0 + buf * BUF_BYTES + OFF_A;
        #pragma unroll
        for (int it = 0; it < 4; it++) {
            const int row = it * 32 + a_row;
            float4 v = aregs[it];
            uint2 hp;
            hp.x = pack2h(__float2half(v.x), __float2half(v.y));
            hp.y = pack2h(__float2half(v.z), __float2half(v.w));
            *reinterpret_cast<uint2*>(bptr + swz64((uint32_t)(row * 64 + a_col4 * 2))) = hp;
        }
    };
    auto issueB = [&](int chunk, int buf) {
        const uint32_t bufb = sbase + SM_BUF0 + buf * BUF_BYTES + OFF_B;
        const int k0 = chunk * KC;
        #pragma unroll
        for (int it = 0; it < 3; it++) {
            int e = tid + it * THREADS;          // 0..671
            if (e < N_HALF * 4) {
                int row = e >> 2;
                int unit = e & 3;
                uint32_t dst = bufb + swz64((uint32_t)(row * 64 + unit * 16));
                cpasync16(dst, wh + (size_t)row * K_PAD + k0 + unit * 8);
            }
        }
        cp_commit();
    };

    // ---- pipeline prologue ----
    ldgA(0);
    stA(0);
    issueB(0, 0);

    for (int i = 0; i < NCHK; i++) {
        const int buf = i & 1;
        const bool more = (i + 1 < NCHK);
        if (more) ldgA(i + 1);                 // LDGs in flight under this chunk's MMAs
        cp_wait0();                            // B(i) landed
        __syncthreads();                       // all warps past chunk i-1; buf^1 free
        if (more) issueB(i + 1, buf ^ 1);

        const uint32_t bufb = sbase + SM_BUF0 + buf * BUF_BYTES;
        #pragma unroll
        for (int k16 = 0; k16 < 2; k16++) {
            const uint32_t ko = (uint32_t)(k16 << 5);
            uint32_t ah[4];
            ldsm4(ah, bufb + OFF_A + (a_swz ^ ko));
            const uint32_t bb = bufb + OFF_B;
            #pragma unroll
            for (int p = 0; p < 10; p += 2) {
                uint32_t bh0[4], bh1[4];
                ldsm4(bh0, bb + p * 1024 + (b_swz ^ ko));
                ldsm4(bh1, bb + (p + 1) * 1024 + (b_swz ^ ko));
                mma16816(acc[2 * p],     ah, bh0[0], bh0[1]);
                mma16816(acc[2 * p + 1], ah, bh0[2], bh0[3]);
                mma16816(acc[2 * p + 2], ah, bh1[0], bh1[1]);
                mma16816(acc[2 * p + 3], ah, bh1[2], bh1[3]);
            }
            uint32_t bh2[2];
            ldsm2(bh2, bb + 10240 + (b2_swz ^ ko));
            mma16816(acc[20], ah, bh2[0], bh2[1]);
        }
        if (more) stA(buf ^ 1);                // convert+store after MMAs (LDG hidden)
    }

    // ---- epilogue ----
    const int chan = (wid < 4) ? c0 : c1;
    if (chan < 0) return;
    const int r0 = wid * 16 + (lane >> 2);           // 0..127
    const int ncol = p0 + (lane & 3) * 2;
    float* o0 = out + ((size_t)(r0 & 63) * C_CH + chan) * P_OUT + ncol;
    float* o1 = out + ((size_t)((r0 + 8) & 63) * C_CH + chan) * P_OUT + ncol;
    const char* bsm = smem + SM_BIAS + 4 * (lane & 3) * 2;
    #pragma unroll
    for (int nf = 0; nf < 21; nf++) {
        float2 bv = *reinterpret_cast<const float2*>(bsm + nf * 32);
        float2 v0 = make_float2(acc[nf][0] + bv.x, acc[nf][1] + bv.y);
        float2 v1 = make_float2(acc[nf][2] + bv.x, acc[nf][3] + bv.y);
        *reinterpret_cast<float2*>(o0 + nf * 8) = v0;
        *reinterpret_cast<float2*>(o1 + nf * 8) = v1;
    }
}

extern "C" void kernel_launch(void* const* d_in, const int* in_sizes, int n_in,
                              void* d_out, int out_size) {
    const float* x        = (const float*)d_in[0];
    const int*   clusters = (const int*)d_in[1];   // int32 or int64; decoded on device
    const float* W        = (const float*)d_in[2];
    const float* bias     = (const float*)d_in[3];
    float*       out      = (float*)d_out;

    cudaFuncSetAttribute(mm_kernel, cudaFuncAttributeMaxDynamicSharedMemorySize, SMEM_TOTAL);

    prep_conv_kernel<<<CONV_BLOCKS + 1, 256>>>(W, clusters);
    dim3 grid(MAX_TASKS, 2);   // (task, N-half)
    mm_kernel<<<grid, THREADS, SMEM_TOTAL>>>(x, bias, out);
}